// round 9
// baseline (speedup 1.0000x reference)
#include <cuda_runtime.h>
#include <cstdint>

#define T_ 30
#define B_ 32
#define N_ 128
#define F_ 128
#define H_ 8
#define TOK (T_*B_*N_)     // 122880
#define ELEMS (TOK*F_)     // 15728640

// ---------------- scratch (static device globals; allocation-free) ----------
__device__ float g_x[ELEMS];
__device__ float g_q[ELEMS];
__device__ float g_k[ELEMS];
__device__ float g_lsv[ELEMS];
__device__ float g_r[ELEMS];
__device__ float g_att[ELEMS];
__device__ float g_mk[B_*N_];     // 1.0 = key active, 0.0 = key masked out

// ---------------- helpers ----------------------------------------------------
__device__ __forceinline__ uint32_t to_tf32(float x) {
    uint32_t r;
    asm("cvt.rna.tf32.f32 %0, %1;" : "=r"(r) : "f"(x));
    return r;
}

// D(16x8) += A(16x8,row) * B(8x8,col)  -- tf32, fp32 accum
__device__ __forceinline__ void mma_tf32(float* d, const uint32_t* a, const uint32_t* b) {
    asm volatile(
        "mma.sync.aligned.m16n8k8.row.col.f32.tf32.tf32.f32 "
        "{%0,%1,%2,%3}, {%4,%5,%6,%7}, {%8,%9}, {%0,%1,%2,%3};"
        : "+f"(d[0]), "+f"(d[1]), "+f"(d[2]), "+f"(d[3])
        : "r"(a[0]), "r"(a[1]), "r"(a[2]), "r"(a[3]), "r"(b[0]), "r"(b[1]));
}

// ---------------- FMA-pipe transcendentals ----------------------------------
// exp for |x| <= ~60 (no clamp; callers guarantee bounded args)
__device__ __forceinline__ float fexp_nc(float x) {
    float y = x * 1.442695041f;
    float kf = y + 12582912.0f;
    int   ki = __float_as_int(kf) - 0x4B400000;
    float f  = y - (kf - 12582912.0f);
    float p = 1.3333558146e-3f;
    p = fmaf(p, f, 9.6181291076e-3f);
    p = fmaf(p, f, 5.5504108664e-2f);
    p = fmaf(p, f, 2.4022650695e-1f);
    p = fmaf(p, f, 6.9314718056e-1f);
    p = fmaf(p, f, 1.0f);
    return p * __int_as_float((ki + 127) << 23);
}
__device__ __forceinline__ float fexp(float x) {
    return fexp_nc(fmaxf(x, -87.0f));
}
__device__ __forceinline__ float frcp_nr(float x) {
    float r = __int_as_float(0x7EF311C3 - __float_as_int(x));
    r = r * (2.0f - x * r);
    r = r * (2.0f - x * r);
    r = r * (2.0f - x * r);
    return r;
}
__device__ __forceinline__ float logsig(float v) {
    float a = fabsf(v);
    float u = fexp(-a);
    float z = u * frcp_nr(2.0f + u);
    float zz = z * z;
    float q = fmaf(zz, 1.0f/9.0f, 1.0f/7.0f);
    q = fmaf(zz, q, 0.2f);
    q = fmaf(zz, q, 1.0f/3.0f);
    q = fmaf(zz, q, 1.0f);
    return fminf(v, 0.0f) - 2.0f * z * q;
}

// ---------------- elementwise kernels ---------------------------------------
__global__ void add_kernel(const float* __restrict__ a, const float* __restrict__ b) {
    int i = blockIdx.x * blockDim.x + threadIdx.x;
    if (i < ELEMS/4) {
        float4 x = ((const float4*)a)[i];
        float4 y = ((const float4*)b)[i];
        ((float4*)g_x)[i] = make_float4(x.x+y.x, x.y+y.y, x.z+y.z, x.w+y.w);
    }
}

__global__ void mask_kernel(const int* __restrict__ mask) {
    int i = blockIdx.x * blockDim.x + threadIdx.x;
    if (i < B_*N_) {
        int any = 0;
        #pragma unroll
        for (int t = 0; t < T_; t++) any |= mask[t*B_*N_ + i];
        g_mk[i] = any ? 1.0f : 0.0f;
    }
}

// ---------------- tf32 mma.sync GEMM (K-chunked, double-buffered) ------------
// C[M,128] = A[M,128] @ W[128,128]^T + bias; mode 0 plain / 1 logsig / 2 +res1-res2
// CTA = 128x128 tile, 256 threads (8 warps), warp tile 64x32.
// K split into 8 chunks of 16; smem = 2 bufs x (A,W) 128x20 words = 41.5KB.
#define KC 16
#define CP 20
#define GEMM_SMEM ((4*128*CP + 128) * 4)   // 41472 bytes

__global__ __launch_bounds__(256)
void gemm_mma(const float* __restrict__ A, const float* __restrict__ W,
              const float* __restrict__ bias, float* __restrict__ C,
              const float* __restrict__ res1, const float* __restrict__ res2,
              int mode) {
    extern __shared__ uint32_t sm[];
    float* biasS = (float*)(sm + 4*128*CP);

    const int tid  = threadIdx.x;
    const int lane = tid & 31;
    const int wid  = tid >> 5;
    const int g  = lane >> 2;
    const int tg = lane & 3;
    const int wm = (wid & 1) * 64;
    const int wn = (wid >> 1) * 32;
    const size_t row0 = (size_t)blockIdx.x * 128;
    const float* Ablk = A + row0*128;

    // per-thread chunk-load coordinates: 512 float4 per matrix per chunk
    const int j0r = tid >> 2,          j0c = (tid & 3) * 4;
    const int j1r = (tid + 256) >> 2,  j1c = tid & 3 ? ((tid & 3) * 4) : 0;  // recompute below properly

    float4 la[2], lw[2];
    // ---- prologue: load chunk 0 ----
    #pragma unroll
    for (int q = 0; q < 2; q++) {
        int j = tid + q*256;
        int r = j >> 2, c4 = j & 3;
        la[q] = *(const float4*)(Ablk + r*128 + c4*4);
        lw[q] = *(const float4*)(W    + r*128 + c4*4);
    }
    #pragma unroll
    for (int q = 0; q < 2; q++) {
        int j = tid + q*256;
        int r = j >> 2, c4 = j & 3;
        uint4 ua = { to_tf32(la[q].x), to_tf32(la[q].y), to_tf32(la[q].z), to_tf32(la[q].w) };
        *(uint4*)(sm + r*CP + c4*4) = ua;
        uint4 uw = { to_tf32(lw[q].x), to_tf32(lw[q].y), to_tf32(lw[q].z), to_tf32(lw[q].w) };
        *(uint4*)(sm + 2*128*CP + r*CP + c4*4) = uw;
    }
    if (tid < 128) biasS[tid] = bias[tid];
    __syncthreads();

    float acc[4][4][4] = {};

    #pragma unroll
    for (int c = 0; c < 8; c++) {
        const int buf = c & 1;
        // issue next chunk's global loads early
        if (c < 7) {
            const int kc = (c + 1) * KC;
            #pragma unroll
            for (int q = 0; q < 2; q++) {
                int j = tid + q*256;
                int r = j >> 2, c4 = j & 3;
                la[q] = *(const float4*)(Ablk + r*128 + kc + c4*4);
                lw[q] = *(const float4*)(W    + r*128 + kc + c4*4);
            }
        }

        const uint32_t* Asb = sm + buf*(128*CP);
        const uint32_t* Wsb = sm + 2*128*CP + buf*(128*CP);
        #pragma unroll
        for (int k0 = 0; k0 < KC; k0 += 8) {
            uint32_t af[4][4], bf[4][2];
            #pragma unroll
            for (int mt = 0; mt < 4; mt++) {
                const uint32_t* ap = Asb + (wm + mt*16 + g)*CP + k0;
                af[mt][0] = ap[tg];
                af[mt][1] = ap[8*CP + tg];
                af[mt][2] = ap[tg + 4];
                af[mt][3] = ap[8*CP + tg + 4];
            }
            #pragma unroll
            for (int nt = 0; nt < 4; nt++) {
                const uint32_t* bp = Wsb + (wn + nt*8 + g)*CP + k0;
                bf[nt][0] = bp[tg];
                bf[nt][1] = bp[tg + 4];
            }
            #pragma unroll
            for (int mt = 0; mt < 4; mt++)
                #pragma unroll
                for (int nt = 0; nt < 4; nt++)
                    mma_tf32(acc[mt][nt], af[mt], bf[nt]);
        }

        // store next chunk into the other buffer
        if (c < 7) {
            const int nbuf = (c + 1) & 1;
            uint32_t* Ad = sm + nbuf*(128*CP);
            uint32_t* Wd = sm + 2*128*CP + nbuf*(128*CP);
            #pragma unroll
            for (int q = 0; q < 2; q++) {
                int j = tid + q*256;
                int r = j >> 2, c4 = j & 3;
                uint4 ua = { to_tf32(la[q].x), to_tf32(la[q].y), to_tf32(la[q].z), to_tf32(la[q].w) };
                *(uint4*)(Ad + r*CP + c4*4) = ua;
                uint4 uw = { to_tf32(lw[q].x), to_tf32(lw[q].y), to_tf32(lw[q].z), to_tf32(lw[q].w) };
                *(uint4*)(Wd + r*CP + c4*4) = uw;
            }
        }
        __syncthreads();
    }

    // ---- epilogue ----
    #pragma unroll
    for (int mt = 0; mt < 4; mt++) {
        #pragma unroll
        for (int nt = 0; nt < 4; nt++) {
            int col = wn + nt*8 + tg*2;
            float b0 = biasS[col], b1 = biasS[col+1];
            #pragma unroll
            for (int half = 0; half < 2; half++) {
                size_t row = row0 + wm + mt*16 + g + half*8;
                float v0 = acc[mt][nt][half*2+0] + b0;
                float v1 = acc[mt][nt][half*2+1] + b1;
                if (mode == 1) {
                    v0 = logsig(v0); v1 = logsig(v1);
                } else if (mode == 2) {
                    size_t idx = row*128 + col;
                    float2 r1 = *(const float2*)(res1 + idx);
                    float2 r2 = *(const float2*)(res2 + idx);
                    v0 += r1.x - r2.x; v1 += r1.y - r2.y;
                }
                *(float2*)(C + row*128 + col) = make_float2(v0, v1);
            }
        }
    }
}

// ---------------- tensor-core attention --------------------------------------
// One CTA per (t,b,h): 128 threads, 4 warps, warp handles 32 query rows.
// One-pass softmax (no max subtraction; scores bounded), mask as 0/1 gate.
// smem layout (floats): qs[128*20] ks[128*20] ls[128*24] pbuf[4][32*36] emk[128]
#define QS_OFF   0
#define KS_OFF   2560
#define LS_OFF   5120
#define PB_OFF   8192
#define EM_OFF   (8192 + 4*1152)      // 12800
#define ATTN_SMEM ((12800 + 128) * 4) // 51712 bytes

__global__ __launch_bounds__(128)
void attn_tc(const float* __restrict__ gq, const float* __restrict__ gk,
             const float* __restrict__ gl, const float* __restrict__ gr,
             float* __restrict__ ga) {
    extern __shared__ float smf[];
    uint32_t* qs = (uint32_t*)(smf + QS_OFF);   // pitch 20, tf32, pre-scaled 0.25
    uint32_t* ks = (uint32_t*)(smf + KS_OFF);   // pitch 20, tf32
    uint32_t* ls = (uint32_t*)(smf + LS_OFF);   // pitch 24, tf32
    float*    em = smf + EM_OFF;

    const int tid  = threadIdx.x;
    const int lane = tid & 31;
    const int wid  = tid >> 5;
    const int g  = lane >> 2;
    const int tg = lane & 3;
    const int blk = blockIdx.x;
    const int h = blk & 7;
    const int b = (blk >> 3) & 31;
    const int t = blk >> 8;
    const int tok0 = (t*B_ + b)*N_;
    uint32_t* pb = (uint32_t*)(smf + PB_OFF) + wid*1152;   // 32 x 36 per warp

    // ---- stage Q (x0.25), K, LSV tiles as tf32 ----
    #pragma unroll
    for (int i = tid; i < 512; i += 128) {
        int token = i >> 2, d4 = i & 3;
        const float* src = gq + ((size_t)(tok0 + token))*F_ + h*16 + d4*4;
        float4 v = *(const float4*)src;
        uint4 u = { to_tf32(v.x*0.25f), to_tf32(v.y*0.25f), to_tf32(v.z*0.25f), to_tf32(v.w*0.25f) };
        *(uint4*)(qs + token*20 + d4*4) = u;
        src = gk + ((size_t)(tok0 + token))*F_ + h*16 + d4*4;
        v = *(const float4*)src;
        uint4 uk = { to_tf32(v.x), to_tf32(v.y), to_tf32(v.z), to_tf32(v.w) };
        *(uint4*)(ks + token*20 + d4*4) = uk;
        src = gl + ((size_t)(tok0 + token))*F_ + h*16 + d4*4;
        v = *(const float4*)src;
        uint4 ul = { to_tf32(v.x), to_tf32(v.y), to_tf32(v.z), to_tf32(v.w) };
        *(uint4*)(ls + token*24 + d4*4) = ul;
    }
    em[tid] = g_mk[b*N_ + tid];
    __syncthreads();

    // ---- Q fragments (resident) ----
    const int row0w = wid * 32;
    uint32_t af[2][2][4];
    #pragma unroll
    for (int mt = 0; mt < 2; mt++)
        #pragma unroll
        for (int ks2 = 0; ks2 < 2; ks2++) {
            int r0 = row0w + mt*16;
            af[mt][ks2][0] = qs[(r0 + g)*20 + ks2*8 + tg];
            af[mt][ks2][1] = qs[(r0 + g + 8)*20 + ks2*8 + tg];
            af[mt][ks2][2] = qs[(r0 + g)*20 + ks2*8 + tg + 4];
            af[mt][ks2][3] = qs[(r0 + g + 8)*20 + ks2*8 + tg + 4];
        }

    float oac[2][2][4] = {};   // [mt][nt2][4] : PV accumulators (unnormalized)
    float ps[2][2] = {};       // [mt][half] rowsum partials

    #pragma unroll
    for (int c = 0; c < 4; c++) {
        const int keys0 = c * 32;
        // --- scores + exp + mask-gate + store P chunk ---
        #pragma unroll
        for (int nt = 0; nt < 4; nt++) {
            const int n0 = keys0 + nt*8;
            uint32_t bf[2][2];
            #pragma unroll
            for (int ks2 = 0; ks2 < 2; ks2++) {
                bf[ks2][0] = ks[(n0 + g)*20 + ks2*8 + tg];
                bf[ks2][1] = ks[(n0 + g)*20 + ks2*8 + tg + 4];
            }
            float2 emv = *(const float2*)(em + n0 + 2*tg);
            #pragma unroll
            for (int mt = 0; mt < 2; mt++) {
                float d[4] = {0.f, 0.f, 0.f, 0.f};
                mma_tf32(d, af[mt][0], bf[0]);
                mma_tf32(d, af[mt][1], bf[1]);
                float e0 = fexp_nc(d[0]) * emv.x;
                float e1 = fexp_nc(d[1]) * emv.y;
                float e2 = fexp_nc(d[2]) * emv.x;
                float e3 = fexp_nc(d[3]) * emv.y;
                ps[mt][0] += e0 + e1;
                ps[mt][1] += e2 + e3;
                uint32_t* p0 = pb + (mt*16 + g)*36 + nt*8 + 2*tg;
                p0[0] = to_tf32(e0); p0[1] = to_tf32(e1);
                uint32_t* p1 = pb + (mt*16 + g + 8)*36 + nt*8 + 2*tg;
                p1[0] = to_tf32(e2); p1[1] = to_tf32(e3);
            }
        }
        __syncwarp();
        // --- PV: O += P_chunk @ LSV_chunk ---
        #pragma unroll
        for (int kk = 0; kk < 4; kk++) {
            uint32_t bl[2][2];
            #pragma unroll
            for (int nt2 = 0; nt2 < 2; nt2++) {
                bl[nt2][0] = ls[(keys0 + kk*8 + tg)*24 + nt2*8 + g];
                bl[nt2][1] = ls[(keys0 + kk*8 + tg + 4)*24 + nt2*8 + g];
            }
            #pragma unroll
            for (int mt = 0; mt < 2; mt++) {
                uint32_t ap[4];
                ap[0] = pb[(mt*16 + g)*36 + kk*8 + tg];
                ap[1] = pb[(mt*16 + g + 8)*36 + kk*8 + tg];
                ap[2] = pb[(mt*16 + g)*36 + kk*8 + tg + 4];
                ap[3] = pb[(mt*16 + g + 8)*36 + kk*8 + tg + 4];
                #pragma unroll
                for (int nt2 = 0; nt2 < 2; nt2++)
                    mma_tf32(oac[mt][nt2], ap, bl[nt2]);
            }
        }
        __syncwarp();
    }

    // ---- rowsum reduce across quad, epilogue ----
    float inv[2][2];
    #pragma unroll
    for (int mt = 0; mt < 2; mt++)
        #pragma unroll
        for (int hf = 0; hf < 2; hf++) {
            float s = ps[mt][hf];
            s += __shfl_xor_sync(0xFFFFFFFF, s, 1);
            s += __shfl_xor_sync(0xFFFFFFFF, s, 2);
            inv[mt][hf] = 1.0f / s;
        }

    #pragma unroll
    for (int mt = 0; mt < 2; mt++)
        #pragma unroll
        for (int hf = 0; hf < 2; hf++) {
            int row = row0w + mt*16 + g + hf*8;
            size_t base = ((size_t)(tok0 + row))*F_ + h*16;
            #pragma unroll
            for (int nt2 = 0; nt2 < 2; nt2++) {
                int col = nt2*8 + 2*tg;
                float2 rv = *(const float2*)(gr + base + col);
                float o0 = rv.x * fexp(oac[mt][nt2][hf*2+0] * inv[mt][hf]);
                float o1 = rv.y * fexp(oac[mt][nt2][hf*2+1] * inv[mt][hf]);
                *(float2*)(ga + base + col) = make_float2(o0, o1);
            }
        }
}

// ---------------- launch -----------------------------------------------------
extern "C" void kernel_launch(void* const* d_in, const int* in_sizes, int n_in,
                              void* d_out, int out_size) {
    const float* input = (const float*)d_in[0];
    const float* ipos  = (const float*)d_in[1];
    const int*   mask  = (const int*)d_in[2];
    const float* Wq = (const float*)d_in[3];  const float* bq = (const float*)d_in[4];
    const float* Wk = (const float*)d_in[5];  const float* bk = (const float*)d_in[6];
    const float* Wv = (const float*)d_in[7];  const float* bv = (const float*)d_in[8];
    const float* Wr = (const float*)d_in[9];  const float* br = (const float*)d_in[10];
    const float* Wc = (const float*)d_in[11]; const float* bc = (const float*)d_in[12];
    float* out = (float*)d_out;

    float *px, *pq, *pk, *pl, *pr, *pa;
    cudaGetSymbolAddress((void**)&px, g_x);
    cudaGetSymbolAddress((void**)&pq, g_q);
    cudaGetSymbolAddress((void**)&pk, g_k);
    cudaGetSymbolAddress((void**)&pl, g_lsv);
    cudaGetSymbolAddress((void**)&pr, g_r);
    cudaGetSymbolAddress((void**)&pa, g_att);

    cudaFuncSetAttribute(gemm_mma, cudaFuncAttributeMaxDynamicSharedMemorySize, GEMM_SMEM);
    cudaFuncSetAttribute(attn_tc,  cudaFuncAttributeMaxDynamicSharedMemorySize, ATTN_SMEM);

    add_kernel<<<(ELEMS/4 + 255)/256, 256>>>(input, ipos);
    mask_kernel<<<(B_*N_ + 127)/128, 128>>>(mask);

    const int MBLK = TOK / 128;   // 960
    gemm_mma<<<MBLK, 256, GEMM_SMEM>>>(px, Wq, bq, pq, nullptr, nullptr, 0);
    gemm_mma<<<MBLK, 256, GEMM_SMEM>>>(px, Wk, bk, pk, nullptr, nullptr, 0);
    gemm_mma<<<MBLK, 256, GEMM_SMEM>>>(px, Wv, bv, pl, nullptr, nullptr, 1);  // log-sigmoid fused
    gemm_mma<<<MBLK, 256, GEMM_SMEM>>>(px, Wr, br, pr, nullptr, nullptr, 0);

    attn_tc<<<T_*B_*H_, 128, ATTN_SMEM>>>(pq, pk, pl, pr, pa);

    gemm_mma<<<MBLK, 256, GEMM_SMEM>>>(pa, Wc, bc, out, input, ipos, 2);
}

// round 12
// speedup vs baseline: 1.1600x; 1.1600x over previous
#include <cuda_runtime.h>
#include <cstdint>

#define T_ 30
#define B_ 32
#define N_ 128
#define F_ 128
#define H_ 8
#define TOK (T_*B_*N_)     // 122880
#define ELEMS (TOK*F_)     // 15728640

// ---------------- scratch (static device globals; allocation-free) ----------
__device__ float g_x[ELEMS];
__device__ float g_q[ELEMS];
__device__ float g_k[ELEMS];
__device__ float g_lsv[ELEMS];
__device__ float g_r[ELEMS];
__device__ float g_att[ELEMS];
__device__ float g_mk[B_*N_];     // 1.0 = key active, 0.0 = key masked out

// ---------------- helpers ----------------------------------------------------
__device__ __forceinline__ uint32_t to_tf32(float x) {
    uint32_t r;
    asm("cvt.rna.tf32.f32 %0, %1;" : "=r"(r) : "f"(x));
    return r;
}

// D(16x8) += A(16x8,row) * B(8x8,col)  -- tf32, fp32 accum
__device__ __forceinline__ void mma_tf32(float* d, const uint32_t* a, const uint32_t* b) {
    asm volatile(
        "mma.sync.aligned.m16n8k8.row.col.f32.tf32.tf32.f32 "
        "{%0,%1,%2,%3}, {%4,%5,%6,%7}, {%8,%9}, {%0,%1,%2,%3};"
        : "+f"(d[0]), "+f"(d[1]), "+f"(d[2]), "+f"(d[3])
        : "r"(a[0]), "r"(a[1]), "r"(a[2]), "r"(a[3]), "r"(b[0]), "r"(b[1]));
}

// ---------------- FMA-pipe transcendentals ----------------------------------
__device__ __forceinline__ float fexp_nc(float x) {
    float y = x * 1.442695041f;
    float kf = y + 12582912.0f;
    int   ki = __float_as_int(kf) - 0x4B400000;
    float f  = y - (kf - 12582912.0f);
    float p = 1.3333558146e-3f;
    p = fmaf(p, f, 9.6181291076e-3f);
    p = fmaf(p, f, 5.5504108664e-2f);
    p = fmaf(p, f, 2.4022650695e-1f);
    p = fmaf(p, f, 6.9314718056e-1f);
    p = fmaf(p, f, 1.0f);
    return p * __int_as_float((ki + 127) << 23);
}
__device__ __forceinline__ float fexp(float x) {
    return fexp_nc(fmaxf(x, -87.0f));
}
__device__ __forceinline__ float frcp_nr(float x) {
    float r = __int_as_float(0x7EF311C3 - __float_as_int(x));
    r = r * (2.0f - x * r);
    r = r * (2.0f - x * r);
    r = r * (2.0f - x * r);
    return r;
}
__device__ __forceinline__ float logsig(float v) {
    float a = fabsf(v);
    float u = fexp(-a);
    float z = u * frcp_nr(2.0f + u);
    float zz = z * z;
    float q = fmaf(zz, 1.0f/9.0f, 1.0f/7.0f);
    q = fmaf(zz, q, 0.2f);
    q = fmaf(zz, q, 1.0f/3.0f);
    q = fmaf(zz, q, 1.0f);
    return fminf(v, 0.0f) - 2.0f * z * q;
}

// ---------------- elementwise kernels ---------------------------------------
__global__ void add_kernel(const float* __restrict__ a, const float* __restrict__ b) {
    int i = blockIdx.x * blockDim.x + threadIdx.x;
    if (i < ELEMS/4) {
        float4 x = ((const float4*)a)[i];
        float4 y = ((const float4*)b)[i];
        ((float4*)g_x)[i] = make_float4(x.x+y.x, x.y+y.y, x.z+y.z, x.w+y.w);
    }
}

__global__ void mask_kernel(const int* __restrict__ mask) {
    int i = blockIdx.x * blockDim.x + threadIdx.x;
    if (i < B_*N_) {
        int any = 0;
        #pragma unroll
        for (int t = 0; t < T_; t++) any |= mask[t*B_*N_ + i];
        g_mk[i] = any ? 1.0f : 0.0f;
    }
}

// ---------------- fused QKVR projection GEMM ---------------------------------
// Computes Cw[M,128] = A[M,128] @ Ww^T + bw for w in {Q,K,V,R}, A staged once.
// CTA = 128 rows; A resident (pitch 132); W single-buffer chunked (KC=32, pitch 36).
// V output (w==2) gets fused log-sigmoid.
#define AP  132
#define WP2 36
#define QKVR_SMEM ((128*AP + 128*WP2 + 512) * 4)   // 88064 bytes

__global__ __launch_bounds__(256, 2)
void gemm_qkvr(const float* __restrict__ A,
               const float* __restrict__ W0, const float* __restrict__ W1,
               const float* __restrict__ W2, const float* __restrict__ W3,
               const float* __restrict__ b0, const float* __restrict__ b1,
               const float* __restrict__ b2, const float* __restrict__ b3,
               float* __restrict__ C0, float* __restrict__ C1,
               float* __restrict__ C2, float* __restrict__ C3) {
    extern __shared__ uint32_t sm[];
    uint32_t* As = sm;                       // 128 x AP
    uint32_t* Ws = sm + 128*AP;              // 128 x WP2 (one 32-wide K chunk)
    float* biasS = (float*)(sm + 128*AP + 128*WP2);   // 4 x 128

    const int tid  = threadIdx.x;
    const int lane = tid & 31;
    const int wid  = tid >> 5;
    const int g  = lane >> 2;
    const int tg = lane & 3;
    const int wm = (wid & 1) * 64;
    const int wn = (wid >> 1) * 32;
    const size_t row0 = (size_t)blockIdx.x * 128;

    // ---- stage A tile once (tf32) + all biases ----
    #pragma unroll
    for (int i = tid; i < 4096; i += 256) {
        int r = i >> 5, c4 = i & 31;
        float4 va = ((const float4*)(A + (row0 + r) * 128))[c4];
        uint4 ta = { to_tf32(va.x), to_tf32(va.y), to_tf32(va.z), to_tf32(va.w) };
        *(uint4*)(As + r*AP + c4*4) = ta;
    }
    if (tid < 128) {
        biasS[tid]       = b0[tid];
        biasS[128 + tid] = b1[tid];
        biasS[256 + tid] = b2[tid];
        biasS[384 + tid] = b3[tid];
    }
    __syncthreads();

    #pragma unroll
    for (int w = 0; w < 4; w++) {
        const float* Wp = (w == 0) ? W0 : (w == 1) ? W1 : (w == 2) ? W2 : W3;
        float* Cp       = (w == 0) ? C0 : (w == 1) ? C1 : (w == 2) ? C2 : C3;

        float acc[4][4][4] = {};

        #pragma unroll
        for (int c = 0; c < 4; c++) {          // K chunks of 32
            const int kc = c * 32;
            float4 lw[4];
            #pragma unroll
            for (int q = 0; q < 4; q++) {
                int j = tid + q*256;           // 0..1023
                int r = j >> 3, c8 = j & 7;
                lw[q] = *(const float4*)(Wp + (size_t)r*128 + kc + c8*4);
            }
            __syncthreads();                   // prior compute done before overwrite
            #pragma unroll
            for (int q = 0; q < 4; q++) {
                int j = tid + q*256;
                int r = j >> 3, c8 = j & 7;
                uint4 uw = { to_tf32(lw[q].x), to_tf32(lw[q].y), to_tf32(lw[q].z), to_tf32(lw[q].w) };
                *(uint4*)(Ws + r*WP2 + c8*4) = uw;
            }
            __syncthreads();

            #pragma unroll
            for (int k0 = 0; k0 < 32; k0 += 8) {
                uint32_t af[4][4], bf[4][2];
                #pragma unroll
                for (int mt = 0; mt < 4; mt++) {
                    const uint32_t* ap = As + (wm + mt*16 + g)*AP + kc + k0;
                    af[mt][0] = ap[tg];
                    af[mt][1] = ap[8*AP + tg];
                    af[mt][2] = ap[tg + 4];
                    af[mt][3] = ap[8*AP + tg + 4];
                }
                #pragma unroll
                for (int nt = 0; nt < 4; nt++) {
                    const uint32_t* bp = Ws + (wn + nt*8 + g)*WP2 + k0;
                    bf[nt][0] = bp[tg];
                    bf[nt][1] = bp[tg + 4];
                }
                #pragma unroll
                for (int mt = 0; mt < 4; mt++)
                    #pragma unroll
                    for (int nt = 0; nt < 4; nt++)
                        mma_tf32(acc[mt][nt], af[mt], bf[nt]);
            }
        }

        // epilogue for matrix w
        #pragma unroll
        for (int mt = 0; mt < 4; mt++) {
            #pragma unroll
            for (int nt = 0; nt < 4; nt++) {
                int col = wn + nt*8 + tg*2;
                float bb0 = biasS[w*128 + col], bb1 = biasS[w*128 + col + 1];
                #pragma unroll
                for (int half = 0; half < 2; half++) {
                    size_t row = row0 + wm + mt*16 + g + half*8;
                    float v0 = acc[mt][nt][half*2+0] + bb0;
                    float v1 = acc[mt][nt][half*2+1] + bb1;
                    if (w == 2) { v0 = logsig(v0); v1 = logsig(v1); }
                    *(float2*)(Cp + row*128 + col) = make_float2(v0, v1);
                }
            }
        }
    }
}

// ---------------- tf32 mma.sync GEMM (R8-proven monolithic) ------------------
// C[M,128] = A[M,128] @ W[128,128]^T + bias; mode 0 plain / 1 logsig / 2 +res1-res2
#define PITCH 132
#define GEMM_SMEM ((128*PITCH*2)*4 + 512)

__global__ __launch_bounds__(256)
void gemm_mma(const float* __restrict__ A, const float* __restrict__ W,
              const float* __restrict__ bias, float* __restrict__ C,
              const float* __restrict__ res1, const float* __restrict__ res2,
              int mode) {
    extern __shared__ uint32_t sm[];
    uint32_t* As = sm;
    uint32_t* Ws = sm + 128*PITCH;
    float* biasS = (float*)(sm + 2*128*PITCH);

    const int tid  = threadIdx.x;
    const int lane = tid & 31;
    const int wid  = tid >> 5;
    const int g  = lane >> 2;
    const int tg = lane & 3;
    const int wm = (wid & 1) * 64;
    const int wn = (wid >> 1) * 32;
    const size_t row0 = (size_t)blockIdx.x * 128;

    #pragma unroll
    for (int i = tid; i < 4096; i += 256) {
        int r = i >> 5, c4 = i & 31;
        float4 va = ((const float4*)(A + (row0 + r) * 128))[c4];
        uint4 ta = { to_tf32(va.x), to_tf32(va.y), to_tf32(va.z), to_tf32(va.w) };
        *(uint4*)(As + r*PITCH + c4*4) = ta;
        float4 vb = ((const float4*)(W + (size_t)r * 128))[c4];
        uint4 tb = { to_tf32(vb.x), to_tf32(vb.y), to_tf32(vb.z), to_tf32(vb.w) };
        *(uint4*)(Ws + r*PITCH + c4*4) = tb;
    }
    if (tid < 128) biasS[tid] = bias[tid];
    __syncthreads();

    float acc[4][4][4] = {};

    #pragma unroll
    for (int k0 = 0; k0 < 128; k0 += 8) {
        uint32_t af[4][4], bf[4][2];
        #pragma unroll
        for (int mt = 0; mt < 4; mt++) {
            const uint32_t* ap = As + (wm + mt*16 + g)*PITCH + k0;
            af[mt][0] = ap[tg];
            af[mt][1] = ap[8*PITCH + tg];
            af[mt][2] = ap[tg + 4];
            af[mt][3] = ap[8*PITCH + tg + 4];
        }
        #pragma unroll
        for (int nt = 0; nt < 4; nt++) {
            const uint32_t* bp = Ws + (wn + nt*8 + g)*PITCH + k0;
            bf[nt][0] = bp[tg];
            bf[nt][1] = bp[tg + 4];
        }
        #pragma unroll
        for (int mt = 0; mt < 4; mt++)
            #pragma unroll
            for (int nt = 0; nt < 4; nt++)
                mma_tf32(acc[mt][nt], af[mt], bf[nt]);
    }

    #pragma unroll
    for (int mt = 0; mt < 4; mt++) {
        #pragma unroll
        for (int nt = 0; nt < 4; nt++) {
            int col = wn + nt*8 + tg*2;
            float b0 = biasS[col], b1 = biasS[col+1];
            #pragma unroll
            for (int half = 0; half < 2; half++) {
                size_t row = row0 + wm + mt*16 + g + half*8;
                float v0 = acc[mt][nt][half*2+0] + b0;
                float v1 = acc[mt][nt][half*2+1] + b1;
                if (mode == 1) {
                    v0 = logsig(v0); v1 = logsig(v1);
                } else if (mode == 2) {
                    size_t idx = row*128 + col;
                    float2 r1 = *(const float2*)(res1 + idx);
                    float2 r2 = *(const float2*)(res2 + idx);
                    v0 += r1.x - r2.x; v1 += r1.y - r2.y;
                }
                *(float2*)(C + row*128 + col) = make_float2(v0, v1);
            }
        }
    }
}

// ---------------- tensor-core attention (R8-proven) --------------------------
// One CTA per (t,b,h): 128 threads, 4 warps, warp handles 32 query rows.
#define QS_OFF   0
#define KS_OFF   2560
#define LS_OFF   5120
#define PB_OFF   8192
#define EM_OFF   (8192 + 4*1152)      // 12800
#define ATTN_SMEM ((12800 + 128) * 4) // 51712 bytes

__global__ __launch_bounds__(128)
void attn_tc(const float* __restrict__ gq, const float* __restrict__ gk,
             const float* __restrict__ gl, const float* __restrict__ gr,
             float* __restrict__ ga) {
    extern __shared__ float smf[];
    uint32_t* qs = (uint32_t*)(smf + QS_OFF);   // pitch 20, tf32, pre-scaled 0.25
    uint32_t* ks = (uint32_t*)(smf + KS_OFF);   // pitch 20, tf32
    uint32_t* ls = (uint32_t*)(smf + LS_OFF);   // pitch 24, tf32
    float*    em = smf + EM_OFF;

    const int tid  = threadIdx.x;
    const int lane = tid & 31;
    const int wid  = tid >> 5;
    const int g  = lane >> 2;
    const int tg = lane & 3;
    const int blk = blockIdx.x;
    const int h = blk & 7;
    const int b = (blk >> 3) & 31;
    const int t = blk >> 8;
    const int tok0 = (t*B_ + b)*N_;
    uint32_t* pb = (uint32_t*)(smf + PB_OFF) + wid*1152;   // 32 x 36 per warp

    #pragma unroll
    for (int i = tid; i < 512; i += 128) {
        int token = i >> 2, d4 = i & 3;
        const float* src = gq + ((size_t)(tok0 + token))*F_ + h*16 + d4*4;
        float4 v = *(const float4*)src;
        uint4 u = { to_tf32(v.x*0.25f), to_tf32(v.y*0.25f), to_tf32(v.z*0.25f), to_tf32(v.w*0.25f) };
        *(uint4*)(qs + token*20 + d4*4) = u;
        src = gk + ((size_t)(tok0 + token))*F_ + h*16 + d4*4;
        v = *(const float4*)src;
        uint4 uk = { to_tf32(v.x), to_tf32(v.y), to_tf32(v.z), to_tf32(v.w) };
        *(uint4*)(ks + token*20 + d4*4) = uk;
        src = gl + ((size_t)(tok0 + token))*F_ + h*16 + d4*4;
        v = *(const float4*)src;
        uint4 ul = { to_tf32(v.x), to_tf32(v.y), to_tf32(v.z), to_tf32(v.w) };
        *(uint4*)(ls + token*24 + d4*4) = ul;
    }
    em[tid] = g_mk[b*N_ + tid];
    __syncthreads();

    const int row0w = wid * 32;
    uint32_t af[2][2][4];
    #pragma unroll
    for (int mt = 0; mt < 2; mt++)
        #pragma unroll
        for (int ks2 = 0; ks2 < 2; ks2++) {
            int r0 = row0w + mt*16;
            af[mt][ks2][0] = qs[(r0 + g)*20 + ks2*8 + tg];
            af[mt][ks2][1] = qs[(r0 + g + 8)*20 + ks2*8 + tg];
            af[mt][ks2][2] = qs[(r0 + g)*20 + ks2*8 + tg + 4];
            af[mt][ks2][3] = qs[(r0 + g + 8)*20 + ks2*8 + tg + 4];
        }

    float oac[2][2][4] = {};
    float ps[2][2] = {};

    #pragma unroll
    for (int c = 0; c < 4; c++) {
        const int keys0 = c * 32;
        #pragma unroll
        for (int nt = 0; nt < 4; nt++) {
            const int n0 = keys0 + nt*8;
            uint32_t bf[2][2];
            #pragma unroll
            for (int ks2 = 0; ks2 < 2; ks2++) {
                bf[ks2][0] = ks[(n0 + g)*20 + ks2*8 + tg];
                bf[ks2][1] = ks[(n0 + g)*20 + ks2*8 + tg + 4];
            }
            float2 emv = *(const float2*)(em + n0 + 2*tg);
            #pragma unroll
            for (int mt = 0; mt < 2; mt++) {
                float d[4] = {0.f, 0.f, 0.f, 0.f};
                mma_tf32(d, af[mt][0], bf[0]);
                mma_tf32(d, af[mt][1], bf[1]);
                float e0 = fexp_nc(d[0]) * emv.x;
                float e1 = fexp_nc(d[1]) * emv.y;
                float e2 = fexp_nc(d[2]) * emv.x;
                float e3 = fexp_nc(d[3]) * emv.y;
                ps[mt][0] += e0 + e1;
                ps[mt][1] += e2 + e3;
                uint32_t* p0 = pb + (mt*16 + g)*36 + nt*8 + 2*tg;
                p0[0] = to_tf32(e0); p0[1] = to_tf32(e1);
                uint32_t* p1 = pb + (mt*16 + g + 8)*36 + nt*8 + 2*tg;
                p1[0] = to_tf32(e2); p1[1] = to_tf32(e3);
            }
        }
        __syncwarp();
        #pragma unroll
        for (int kk = 0; kk < 4; kk++) {
            uint32_t bl[2][2];
            #pragma unroll
            for (int nt2 = 0; nt2 < 2; nt2++) {
                bl[nt2][0] = ls[(keys0 + kk*8 + tg)*24 + nt2*8 + g];
                bl[nt2][1] = ls[(keys0 + kk*8 + tg + 4)*24 + nt2*8 + g];
            }
            #pragma unroll
            for (int mt = 0; mt < 2; mt++) {
                uint32_t ap[4];
                ap[0] = pb[(mt*16 + g)*36 + kk*8 + tg];
                ap[1] = pb[(mt*16 + g + 8)*36 + kk*8 + tg];
                ap[2] = pb[(mt*16 + g)*36 + kk*8 + tg + 4];
                ap[3] = pb[(mt*16 + g + 8)*36 + kk*8 + tg + 4];
                #pragma unroll
                for (int nt2 = 0; nt2 < 2; nt2++)
                    mma_tf32(oac[mt][nt2], ap, bl[nt2]);
            }
        }
        __syncwarp();
    }

    float inv[2][2];
    #pragma unroll
    for (int mt = 0; mt < 2; mt++)
        #pragma unroll
        for (int hf = 0; hf < 2; hf++) {
            float s = ps[mt][hf];
            s += __shfl_xor_sync(0xFFFFFFFF, s, 1);
            s += __shfl_xor_sync(0xFFFFFFFF, s, 2);
            inv[mt][hf] = 1.0f / s;
        }

    #pragma unroll
    for (int mt = 0; mt < 2; mt++)
        #pragma unroll
        for (int hf = 0; hf < 2; hf++) {
            int row = row0w + mt*16 + g + hf*8;
            size_t base = ((size_t)(tok0 + row))*F_ + h*16;
            #pragma unroll
            for (int nt2 = 0; nt2 < 2; nt2++) {
                int col = nt2*8 + 2*tg;
                float2 rv = *(const float2*)(gr + base + col);
                float o0 = rv.x * fexp(oac[mt][nt2][hf*2+0] * inv[mt][hf]);
                float o1 = rv.y * fexp(oac[mt][nt2][hf*2+1] * inv[mt][hf]);
                *(float2*)(ga + base + col) = make_float2(o0, o1);
            }
        }
}

// ---------------- launch -----------------------------------------------------
extern "C" void kernel_launch(void* const* d_in, const int* in_sizes, int n_in,
                              void* d_out, int out_size) {
    const float* input = (const float*)d_in[0];
    const float* ipos  = (const float*)d_in[1];
    const int*   mask  = (const int*)d_in[2];
    const float* Wq = (const float*)d_in[3];  const float* bq = (const float*)d_in[4];
    const float* Wk = (const float*)d_in[5];  const float* bk = (const float*)d_in[6];
    const float* Wv = (const float*)d_in[7];  const float* bv = (const float*)d_in[8];
    const float* Wr = (const float*)d_in[9];  const float* br = (const float*)d_in[10];
    const float* Wc = (const float*)d_in[11]; const float* bc = (const float*)d_in[12];
    float* out = (float*)d_out;

    float *px, *pq, *pk, *pl, *pr, *pa;
    cudaGetSymbolAddress((void**)&px, g_x);
    cudaGetSymbolAddress((void**)&pq, g_q);
    cudaGetSymbolAddress((void**)&pk, g_k);
    cudaGetSymbolAddress((void**)&pl, g_lsv);
    cudaGetSymbolAddress((void**)&pr, g_r);
    cudaGetSymbolAddress((void**)&pa, g_att);

    cudaFuncSetAttribute(gemm_qkvr, cudaFuncAttributeMaxDynamicSharedMemorySize, QKVR_SMEM);
    cudaFuncSetAttribute(gemm_mma,  cudaFuncAttributeMaxDynamicSharedMemorySize, GEMM_SMEM);
    cudaFuncSetAttribute(attn_tc,   cudaFuncAttributeMaxDynamicSharedMemorySize, ATTN_SMEM);

    add_kernel<<<(ELEMS/4 + 255)/256, 256>>>(input, ipos);
    mask_kernel<<<(B_*N_ + 127)/128, 128>>>(mask);

    const int MBLK = TOK / 128;   // 960
    gemm_qkvr<<<MBLK, 256, QKVR_SMEM>>>(px, Wq, Wk, Wv, Wr,
                                        bq, bk, bv, br,
                                        pq, pk, pl, pr);

    attn_tc<<<T_*B_*H_, 128, ATTN_SMEM>>>(pq, pk, pl, pr, pa);

    gemm_mma<<<MBLK, 256, GEMM_SMEM>>>(pa, Wc, bc, out, input, ipos, 2);
}

// round 15
// speedup vs baseline: 1.2070x; 1.0405x over previous
#include <cuda_runtime.h>
#include <cstdint>

#define T_ 30
#define B_ 32
#define N_ 128
#define F_ 128
#define H_ 8
#define TOK (T_*B_*N_)     // 122880
#define ELEMS (TOK*F_)     // 15728640

// ---------------- scratch (static device globals; allocation-free) ----------
__device__ float g_q[ELEMS];
__device__ float g_k[ELEMS];
__device__ float g_lsv[ELEMS];
__device__ float g_r[ELEMS];
__device__ float g_att[ELEMS];
__device__ float g_mk[B_*N_];     // 1.0 = key active, 0.0 = key masked out

// ---------------- helpers ----------------------------------------------------
__device__ __forceinline__ uint32_t to_tf32(float x) {
    uint32_t r;
    asm("cvt.rna.tf32.f32 %0, %1;" : "=r"(r) : "f"(x));
    return r;
}

// D(16x8) += A(16x8,row) * B(8x8,col)  -- tf32, fp32 accum
__device__ __forceinline__ void mma_tf32(float* d, const uint32_t* a, const uint32_t* b) {
    asm volatile(
        "mma.sync.aligned.m16n8k8.row.col.f32.tf32.tf32.f32 "
        "{%0,%1,%2,%3}, {%4,%5,%6,%7}, {%8,%9}, {%0,%1,%2,%3};"
        : "+f"(d[0]), "+f"(d[1]), "+f"(d[2]), "+f"(d[3])
        : "r"(a[0]), "r"(a[1]), "r"(a[2]), "r"(a[3]), "r"(b[0]), "r"(b[1]));
}

// ---------------- FMA-pipe transcendentals ----------------------------------
__device__ __forceinline__ float fexp_nc(float x) {
    float y = x * 1.442695041f;
    float kf = y + 12582912.0f;
    int   ki = __float_as_int(kf) - 0x4B400000;
    float f  = y - (kf - 12582912.0f);
    float p = 1.3333558146e-3f;
    p = fmaf(p, f, 9.6181291076e-3f);
    p = fmaf(p, f, 5.5504108664e-2f);
    p = fmaf(p, f, 2.4022650695e-1f);
    p = fmaf(p, f, 6.9314718056e-1f);
    p = fmaf(p, f, 1.0f);
    return p * __int_as_float((ki + 127) << 23);
}
__device__ __forceinline__ float fexp(float x) {
    return fexp_nc(fmaxf(x, -87.0f));
}
__device__ __forceinline__ float frcp_nr(float x) {
    float r = __int_as_float(0x7EF311C3 - __float_as_int(x));
    r = r * (2.0f - x * r);
    r = r * (2.0f - x * r);
    r = r * (2.0f - x * r);
    return r;
}
__device__ __forceinline__ float logsig(float v) {
    float a = fabsf(v);
    float u = fexp(-a);
    float z = u * frcp_nr(2.0f + u);
    float zz = z * z;
    float q = fmaf(zz, 1.0f/9.0f, 1.0f/7.0f);
    q = fmaf(zz, q, 0.2f);
    q = fmaf(zz, q, 1.0f/3.0f);
    q = fmaf(zz, q, 1.0f);
    return fminf(v, 0.0f) - 2.0f * z * q;
}

// ---------------- mask kernel ------------------------------------------------
__global__ void mask_kernel(const int* __restrict__ mask) {
    int i = blockIdx.x * blockDim.x + threadIdx.x;
    if (i < B_*N_) {
        int any = 0;
        #pragma unroll
        for (int t = 0; t < T_; t++) any |= mask[t*B_*N_ + i];
        g_mk[i] = any ? 1.0f : 0.0f;
    }
}

// ---------------- fused QKVR projection GEMM (x = input + ipos fused) --------
// Cw[M,128] = (input+ipos)[M,128] @ Ww^T + bw for w in {Q,K,V,R}.
// A staged once per CTA; W single-buffer chunked (KC=32). V gets log-sigmoid.
#define AP  132
#define WP2 36
#define QKVR_SMEM ((128*AP + 128*WP2 + 512) * 4)   // 88064 bytes

__global__ __launch_bounds__(256, 2)
void gemm_qkvr(const float* __restrict__ input, const float* __restrict__ ipos,
               const float* __restrict__ W0, const float* __restrict__ W1,
               const float* __restrict__ W2, const float* __restrict__ W3,
               const float* __restrict__ b0, const float* __restrict__ b1,
               const float* __restrict__ b2, const float* __restrict__ b3,
               float* __restrict__ C0, float* __restrict__ C1,
               float* __restrict__ C2, float* __restrict__ C3) {
    extern __shared__ uint32_t sm[];
    uint32_t* As = sm;                       // 128 x AP
    uint32_t* Ws = sm + 128*AP;              // 128 x WP2 (one 32-wide K chunk)
    float* biasS = (float*)(sm + 128*AP + 128*WP2);   // 4 x 128

    const int tid  = threadIdx.x;
    const int lane = tid & 31;
    const int wid  = tid >> 5;
    const int g  = lane >> 2;
    const int tg = lane & 3;
    const int wm = (wid & 1) * 64;
    const int wn = (wid >> 1) * 32;
    const size_t row0 = (size_t)blockIdx.x * 128;

    // ---- stage A = input + ipos (tf32) + all biases ----
    #pragma unroll
    for (int i = tid; i < 4096; i += 256) {
        int r = i >> 5, c4 = i & 31;
        size_t off = (row0 + r) * 128 + c4*4;
        float4 va = *(const float4*)(input + off);
        float4 vb = *(const float4*)(ipos + off);
        uint4 ta = { to_tf32(va.x + vb.x), to_tf32(va.y + vb.y),
                     to_tf32(va.z + vb.z), to_tf32(va.w + vb.w) };
        *(uint4*)(As + r*AP + c4*4) = ta;
    }
    if (tid < 128) {
        biasS[tid]       = b0[tid];
        biasS[128 + tid] = b1[tid];
        biasS[256 + tid] = b2[tid];
        biasS[384 + tid] = b3[tid];
    }
    __syncthreads();

    #pragma unroll
    for (int w = 0; w < 4; w++) {
        const float* Wp = (w == 0) ? W0 : (w == 1) ? W1 : (w == 2) ? W2 : W3;
        float* Cp       = (w == 0) ? C0 : (w == 1) ? C1 : (w == 2) ? C2 : C3;

        float acc[4][4][4] = {};

        #pragma unroll
        for (int c = 0; c < 4; c++) {          // K chunks of 32
            const int kc = c * 32;
            float4 lw[4];
            #pragma unroll
            for (int q = 0; q < 4; q++) {
                int j = tid + q*256;           // 0..1023
                int r = j >> 3, c8 = j & 7;
                lw[q] = *(const float4*)(Wp + (size_t)r*128 + kc + c8*4);
            }
            __syncthreads();                   // prior compute done before overwrite
            #pragma unroll
            for (int q = 0; q < 4; q++) {
                int j = tid + q*256;
                int r = j >> 3, c8 = j & 7;
                uint4 uw = { to_tf32(lw[q].x), to_tf32(lw[q].y), to_tf32(lw[q].z), to_tf32(lw[q].w) };
                *(uint4*)(Ws + r*WP2 + c8*4) = uw;
            }
            __syncthreads();

            #pragma unroll
            for (int k0 = 0; k0 < 32; k0 += 8) {
                uint32_t af[4][4], bf[4][2];
                #pragma unroll
                for (int mt = 0; mt < 4; mt++) {
                    const uint32_t* ap = As + (wm + mt*16 + g)*AP + kc + k0;
                    af[mt][0] = ap[tg];
                    af[mt][1] = ap[8*AP + tg];
                    af[mt][2] = ap[tg + 4];
                    af[mt][3] = ap[8*AP + tg + 4];
                }
                #pragma unroll
                for (int nt = 0; nt < 4; nt++) {
                    const uint32_t* bp = Ws + (wn + nt*8 + g)*WP2 + k0;
                    bf[nt][0] = bp[tg];
                    bf[nt][1] = bp[tg + 4];
                }
                #pragma unroll
                for (int mt = 0; mt < 4; mt++)
                    #pragma unroll
                    for (int nt = 0; nt < 4; nt++)
                        mma_tf32(acc[mt][nt], af[mt], bf[nt]);
            }
        }

        // epilogue for matrix w
        #pragma unroll
        for (int mt = 0; mt < 4; mt++) {
            #pragma unroll
            for (int nt = 0; nt < 4; nt++) {
                int col = wn + nt*8 + tg*2;
                float bb0 = biasS[w*128 + col], bb1 = biasS[w*128 + col + 1];
                #pragma unroll
                for (int half = 0; half < 2; half++) {
                    size_t row = row0 + wm + mt*16 + g + half*8;
                    float v0 = acc[mt][nt][half*2+0] + bb0;
                    float v1 = acc[mt][nt][half*2+1] + bb1;
                    if (w == 2) { v0 = logsig(v0); v1 = logsig(v1); }
                    *(float2*)(Cp + row*128 + col) = make_float2(v0, v1);
                }
            }
        }
    }
}

// ---------------- tf32 mma.sync GEMM (R8-proven monolithic) ------------------
// C[M,128] = A[M,128] @ W[128,128]^T + bias; mode 0 plain / 2 +res1-res2
#define PITCH 132
#define GEMM_SMEM ((128*PITCH*2)*4 + 512)

__global__ __launch_bounds__(256)
void gemm_mma(const float* __restrict__ A, const float* __restrict__ W,
              const float* __restrict__ bias, float* __restrict__ C,
              const float* __restrict__ res1, const float* __restrict__ res2,
              int mode) {
    extern __shared__ uint32_t sm[];
    uint32_t* As = sm;
    uint32_t* Ws = sm + 128*PITCH;
    float* biasS = (float*)(sm + 2*128*PITCH);

    const int tid  = threadIdx.x;
    const int lane = tid & 31;
    const int wid  = tid >> 5;
    const int g  = lane >> 2;
    const int tg = lane & 3;
    const int wm = (wid & 1) * 64;
    const int wn = (wid >> 1) * 32;
    const size_t row0 = (size_t)blockIdx.x * 128;

    #pragma unroll
    for (int i = tid; i < 4096; i += 256) {
        int r = i >> 5, c4 = i & 31;
        float4 va = ((const float4*)(A + (row0 + r) * 128))[c4];
        uint4 ta = { to_tf32(va.x), to_tf32(va.y), to_tf32(va.z), to_tf32(va.w) };
        *(uint4*)(As + r*PITCH + c4*4) = ta;
        float4 vb = ((const float4*)(W + (size_t)r * 128))[c4];
        uint4 tb = { to_tf32(vb.x), to_tf32(vb.y), to_tf32(vb.z), to_tf32(vb.w) };
        *(uint4*)(Ws + r*PITCH + c4*4) = tb;
    }
    if (tid < 128) biasS[tid] = bias[tid];
    __syncthreads();

    float acc[4][4][4] = {};

    #pragma unroll
    for (int k0 = 0; k0 < 128; k0 += 8) {
        uint32_t af[4][4], bf[4][2];
        #pragma unroll
        for (int mt = 0; mt < 4; mt++) {
            const uint32_t* ap = As + (wm + mt*16 + g)*PITCH + k0;
            af[mt][0] = ap[tg];
            af[mt][1] = ap[8*PITCH + tg];
            af[mt][2] = ap[tg + 4];
            af[mt][3] = ap[8*PITCH + tg + 4];
        }
        #pragma unroll
        for (int nt = 0; nt < 4; nt++) {
            const uint32_t* bp = Ws + (wn + nt*8 + g)*PITCH + k0;
            bf[nt][0] = bp[tg];
            bf[nt][1] = bp[tg + 4];
        }
        #pragma unroll
        for (int mt = 0; mt < 4; mt++)
            #pragma unroll
            for (int nt = 0; nt < 4; nt++)
                mma_tf32(acc[mt][nt], af[mt], bf[nt]);
    }

    #pragma unroll
    for (int mt = 0; mt < 4; mt++) {
        #pragma unroll
        for (int nt = 0; nt < 4; nt++) {
            int col = wn + nt*8 + tg*2;
            float b0 = biasS[col], b1 = biasS[col+1];
            #pragma unroll
            for (int half = 0; half < 2; half++) {
                size_t row = row0 + wm + mt*16 + g + half*8;
                float v0 = acc[mt][nt][half*2+0] + b0;
                float v1 = acc[mt][nt][half*2+1] + b1;
                if (mode == 1) {
                    v0 = logsig(v0); v1 = logsig(v1);
                } else if (mode == 2) {
                    size_t idx = row*128 + col;
                    float2 r1 = *(const float2*)(res1 + idx);
                    float2 r2 = *(const float2*)(res2 + idx);
                    v0 += r1.x - r2.x; v1 += r1.y - r2.y;
                }
                *(float2*)(C + row*128 + col) = make_float2(v0, v1);
            }
        }
    }
}

// ---------------- tensor-core attention (R12-proven, P smem buffer) ----------
// One CTA per (t,b,h): 128 threads, 4 warps, warp handles 32 query rows.
#define QS_OFF   0
#define KS_OFF   2560
#define LS_OFF   5120
#define PB_OFF   8192
#define EM_OFF   (8192 + 4*1152)      // 12800
#define ATTN_SMEM ((12800 + 128) * 4) // 51712 bytes

__global__ __launch_bounds__(128)
void attn_tc(const float* __restrict__ gq, const float* __restrict__ gk,
             const float* __restrict__ gl, const float* __restrict__ gr,
             float* __restrict__ ga) {
    extern __shared__ float smf[];
    uint32_t* qs = (uint32_t*)(smf + QS_OFF);   // pitch 20, tf32, pre-scaled 0.25
    uint32_t* ks = (uint32_t*)(smf + KS_OFF);   // pitch 20, tf32
    uint32_t* ls = (uint32_t*)(smf + LS_OFF);   // pitch 24, tf32
    float*    em = smf + EM_OFF;

    const int tid  = threadIdx.x;
    const int lane = tid & 31;
    const int wid  = tid >> 5;
    const int g  = lane >> 2;
    const int tg = lane & 3;
    const int blk = blockIdx.x;
    const int h = blk & 7;
    const int b = (blk >> 3) & 31;
    const int t = blk >> 8;
    const int tok0 = (t*B_ + b)*N_;
    uint32_t* pb = (uint32_t*)(smf + PB_OFF) + wid*1152;   // 32 x 36 per warp

    #pragma unroll
    for (int i = tid; i < 512; i += 128) {
        int token = i >> 2, d4 = i & 3;
        const float* src = gq + ((size_t)(tok0 + token))*F_ + h*16 + d4*4;
        float4 v = *(const float4*)src;
        uint4 u = { to_tf32(v.x*0.25f), to_tf32(v.y*0.25f), to_tf32(v.z*0.25f), to_tf32(v.w*0.25f) };
        *(uint4*)(qs + token*20 + d4*4) = u;
        src = gk + ((size_t)(tok0 + token))*F_ + h*16 + d4*4;
        v = *(const float4*)src;
        uint4 uk = { to_tf32(v.x), to_tf32(v.y), to_tf32(v.z), to_tf32(v.w) };
        *(uint4*)(ks + token*20 + d4*4) = uk;
        src = gl + ((size_t)(tok0 + token))*F_ + h*16 + d4*4;
        v = *(const float4*)src;
        uint4 ul = { to_tf32(v.x), to_tf32(v.y), to_tf32(v.z), to_tf32(v.w) };
        *(uint4*)(ls + token*24 + d4*4) = ul;
    }
    em[tid] = g_mk[b*N_ + tid];
    __syncthreads();

    const int row0w = wid * 32;
    uint32_t af[2][2][4];
    #pragma unroll
    for (int mt = 0; mt < 2; mt++)
        #pragma unroll
        for (int ks2 = 0; ks2 < 2; ks2++) {
            int r0 = row0w + mt*16;
            af[mt][ks2][0] = qs[(r0 + g)*20 + ks2*8 + tg];
            af[mt][ks2][1] = qs[(r0 + g + 8)*20 + ks2*8 + tg];
            af[mt][ks2][2] = qs[(r0 + g)*20 + ks2*8 + tg + 4];
            af[mt][ks2][3] = qs[(r0 + g + 8)*20 + ks2*8 + tg + 4];
        }

    float oac[2][2][4] = {};
    float ps[2][2] = {};

    #pragma unroll
    for (int c = 0; c < 4; c++) {
        const int keys0 = c * 32;
        #pragma unroll
        for (int nt = 0; nt < 4; nt++) {
            const int n0 = keys0 + nt*8;
            uint32_t bf[2][2];
            #pragma unroll
            for (int ks2 = 0; ks2 < 2; ks2++) {
                bf[ks2][0] = ks[(n0 + g)*20 + ks2*8 + tg];
                bf[ks2][1] = ks[(n0 + g)*20 + ks2*8 + tg + 4];
            }
            float2 emv = *(const float2*)(em + n0 + 2*tg);
            #pragma unroll
            for (int mt = 0; mt < 2; mt++) {
                float d[4] = {0.f, 0.f, 0.f, 0.f};
                mma_tf32(d, af[mt][0], bf[0]);
                mma_tf32(d, af[mt][1], bf[1]);
                float e0 = fexp_nc(d[0]) * emv.x;
                float e1 = fexp_nc(d[1]) * emv.y;
                float e2 = fexp_nc(d[2]) * emv.x;
                float e3 = fexp_nc(d[3]) * emv.y;
                ps[mt][0] += e0 + e1;
                ps[mt][1] += e2 + e3;
                uint32_t* p0 = pb + (mt*16 + g)*36 + nt*8 + 2*tg;
                p0[0] = to_tf32(e0); p0[1] = to_tf32(e1);
                uint32_t* p1 = pb + (mt*16 + g + 8)*36 + nt*8 + 2*tg;
                p1[0] = to_tf32(e2); p1[1] = to_tf32(e3);
            }
        }
        __syncwarp();
        #pragma unroll
        for (int kk = 0; kk < 4; kk++) {
            uint32_t bl[2][2];
            #pragma unroll
            for (int nt2 = 0; nt2 < 2; nt2++) {
                bl[nt2][0] = ls[(keys0 + kk*8 + tg)*24 + nt2*8 + g];
                bl[nt2][1] = ls[(keys0 + kk*8 + tg + 4)*24 + nt2*8 + g];
            }
            #pragma unroll
            for (int mt = 0; mt < 2; mt++) {
                uint32_t ap[4];
                ap[0] = pb[(mt*16 + g)*36 + kk*8 + tg];
                ap[1] = pb[(mt*16 + g + 8)*36 + kk*8 + tg];
                ap[2] = pb[(mt*16 + g)*36 + kk*8 + tg + 4];
                ap[3] = pb[(mt*16 + g + 8)*36 + kk*8 + tg + 4];
                #pragma unroll
                for (int nt2 = 0; nt2 < 2; nt2++)
                    mma_tf32(oac[mt][nt2], ap, bl[nt2]);
            }
        }
        __syncwarp();
    }

    float inv[2][2];
    #pragma unroll
    for (int mt = 0; mt < 2; mt++)
        #pragma unroll
        for (int hf = 0; hf < 2; hf++) {
            float s = ps[mt][hf];
            s += __shfl_xor_sync(0xFFFFFFFF, s, 1);
            s += __shfl_xor_sync(0xFFFFFFFF, s, 2);
            inv[mt][hf] = 1.0f / s;
        }

    #pragma unroll
    for (int mt = 0; mt < 2; mt++)
        #pragma unroll
        for (int hf = 0; hf < 2; hf++) {
            int row = row0w + mt*16 + g + hf*8;
            size_t base = ((size_t)(tok0 + row))*F_ + h*16;
            #pragma unroll
            for (int nt2 = 0; nt2 < 2; nt2++) {
                int col = nt2*8 + 2*tg;
                float2 rv = *(const float2*)(gr + base + col);
                float o0 = rv.x * fexp(oac[mt][nt2][hf*2+0] * inv[mt][hf]);
                float o1 = rv.y * fexp(oac[mt][nt2][hf*2+1] * inv[mt][hf]);
                *(float2*)(ga + base + col) = make_float2(o0, o1);
            }
        }
}

// ---------------- launch -----------------------------------------------------
extern "C" void kernel_launch(void* const* d_in, const int* in_sizes, int n_in,
                              void* d_out, int out_size) {
    const float* input = (const float*)d_in[0];
    const float* ipos  = (const float*)d_in[1];
    const int*   mask  = (const int*)d_in[2];
    const float* Wq = (const float*)d_in[3];  const float* bq = (const float*)d_in[4];
    const float* Wk = (const float*)d_in[5];  const float* bk = (const float*)d_in[6];
    const float* Wv = (const float*)d_in[7];  const float* bv = (const float*)d_in[8];
    const float* Wr = (const float*)d_in[9];  const float* br = (const float*)d_in[10];
    const float* Wc = (const float*)d_in[11]; const float* bc = (const float*)d_in[12];
    float* out = (float*)d_out;

    float *pq, *pk, *pl, *pr, *pa;
    cudaGetSymbolAddress((void**)&pq, g_q);
    cudaGetSymbolAddress((void**)&pk, g_k);
    cudaGetSymbolAddress((void**)&pl, g_lsv);
    cudaGetSymbolAddress((void**)&pr, g_r);
    cudaGetSymbolAddress((void**)&pa, g_att);

    cudaFuncSetAttribute(gemm_qkvr, cudaFuncAttributeMaxDynamicSharedMemorySize, QKVR_SMEM);
    cudaFuncSetAttribute(gemm_mma,  cudaFuncAttributeMaxDynamicSharedMemorySize, GEMM_SMEM);
    cudaFuncSetAttribute(attn_tc,   cudaFuncAttributeMaxDynamicSharedMemorySize, ATTN_SMEM);

    mask_kernel<<<(B_*N_ + 127)/128, 128>>>(mask);

    const int MBLK = TOK / 128;   // 960
    gemm_qkvr<<<MBLK, 256, QKVR_SMEM>>>(input, ipos, Wq, Wk, Wv, Wr,
                                        bq, bk, bv, br,
                                        pq, pk, pl, pr);

    attn_tc<<<T_*B_*H_, 128, ATTN_SMEM>>>(pq, pk, pl, pr, pa);

    gemm_mma<<<MBLK, 256, GEMM_SMEM>>>(pa, Wc, bc, out, input, ipos, 2);
}

// round 16
// speedup vs baseline: 1.2532x; 1.0382x over previous
#include <cuda_runtime.h>
#include <cstdint>

#define T_ 30
#define B_ 32
#define N_ 128
#define F_ 128
#define H_ 8
#define TOK (T_*B_*N_)     // 122880
#define ELEMS (TOK*F_)     // 15728640

// ---------------- scratch (static device globals; allocation-free) ----------
__device__ float g_q[ELEMS];
__device__ float g_k[ELEMS];
__device__ float g_lsv[ELEMS];
__device__ float g_r[ELEMS];
__device__ float g_att[ELEMS];
__device__ float g_mk[B_*N_];     // 1.0 = key active, 0.0 = key masked out

// ---------------- helpers ----------------------------------------------------
__device__ __forceinline__ uint32_t to_tf32(float x) {
    uint32_t r;
    asm("cvt.rna.tf32.f32 %0, %1;" : "=r"(r) : "f"(x));
    return r;
}

// D(16x8) += A(16x8,row) * B(8x8,col)  -- tf32, fp32 accum
__device__ __forceinline__ void mma_tf32(float* d, const uint32_t* a, const uint32_t* b) {
    asm volatile(
        "mma.sync.aligned.m16n8k8.row.col.f32.tf32.tf32.f32 "
        "{%0,%1,%2,%3}, {%4,%5,%6,%7}, {%8,%9}, {%0,%1,%2,%3};"
        : "+f"(d[0]), "+f"(d[1]), "+f"(d[2]), "+f"(d[3])
        : "r"(a[0]), "r"(a[1]), "r"(a[2]), "r"(a[3]), "r"(b[0]), "r"(b[1]));
}

// ---------------- FMA-pipe transcendentals ----------------------------------
__device__ __forceinline__ float fexp_nc(float x) {
    float y = x * 1.442695041f;
    float kf = y + 12582912.0f;
    int   ki = __float_as_int(kf) - 0x4B400000;
    float f  = y - (kf - 12582912.0f);
    float p = 1.3333558146e-3f;
    p = fmaf(p, f, 9.6181291076e-3f);
    p = fmaf(p, f, 5.5504108664e-2f);
    p = fmaf(p, f, 2.4022650695e-1f);
    p = fmaf(p, f, 6.9314718056e-1f);
    p = fmaf(p, f, 1.0f);
    return p * __int_as_float((ki + 127) << 23);
}
__device__ __forceinline__ float fexp(float x) {
    return fexp_nc(fmaxf(x, -87.0f));
}
__device__ __forceinline__ float frcp_nr(float x) {
    float r = __int_as_float(0x7EF311C3 - __float_as_int(x));
    r = r * (2.0f - x * r);
    r = r * (2.0f - x * r);
    r = r * (2.0f - x * r);
    return r;
}
__device__ __forceinline__ float logsig(float v) {
    float a = fabsf(v);
    float u = fexp(-a);
    float z = u * frcp_nr(2.0f + u);
    float zz = z * z;
    float q = fmaf(zz, 1.0f/9.0f, 1.0f/7.0f);
    q = fmaf(zz, q, 0.2f);
    q = fmaf(zz, q, 1.0f/3.0f);
    q = fmaf(zz, q, 1.0f);
    return fminf(v, 0.0f) - 2.0f * z * q;
}

// ---------------- mask kernel ------------------------------------------------
__global__ void mask_kernel(const int* __restrict__ mask) {
    int i = blockIdx.x * blockDim.x + threadIdx.x;
    if (i < B_*N_) {
        int any = 0;
        #pragma unroll
        for (int t = 0; t < T_; t++) any |= mask[t*B_*N_ + i];
        g_mk[i] = any ? 1.0f : 0.0f;
    }
}

// ---------------- fused QKVR projection GEMM (x = input + ipos fused) --------
// Cw[M,128] = (input+ipos)[M,128] @ Ww^T + bw for w in {Q,K,V,R}.
// A staged once per CTA; W single-buffer chunked (KC=32). V gets log-sigmoid.
#define AP  132
#define WP2 36
#define QKVR_SMEM ((128*AP + 128*WP2 + 512) * 4)   // 88064 bytes

__global__ __launch_bounds__(256, 2)
void gemm_qkvr(const float* __restrict__ input, const float* __restrict__ ipos,
               const float* __restrict__ W0, const float* __restrict__ W1,
               const float* __restrict__ W2, const float* __restrict__ W3,
               const float* __restrict__ b0, const float* __restrict__ b1,
               const float* __restrict__ b2, const float* __restrict__ b3,
               float* __restrict__ C0, float* __restrict__ C1,
               float* __restrict__ C2, float* __restrict__ C3) {
    extern __shared__ uint32_t sm[];
    uint32_t* As = sm;                       // 128 x AP
    uint32_t* Ws = sm + 128*AP;              // 128 x WP2 (one 32-wide K chunk)
    float* biasS = (float*)(sm + 128*AP + 128*WP2);   // 4 x 128

    const int tid  = threadIdx.x;
    const int lane = tid & 31;
    const int wid  = tid >> 5;
    const int g  = lane >> 2;
    const int tg = lane & 3;
    const int wm = (wid & 1) * 64;
    const int wn = (wid >> 1) * 32;
    const size_t row0 = (size_t)blockIdx.x * 128;

    // ---- stage A = input + ipos (tf32) + all biases ----
    #pragma unroll
    for (int i = tid; i < 4096; i += 256) {
        int r = i >> 5, c4 = i & 31;
        size_t off = (row0 + r) * 128 + c4*4;
        float4 va = *(const float4*)(input + off);
        float4 vb = *(const float4*)(ipos + off);
        uint4 ta = { to_tf32(va.x + vb.x), to_tf32(va.y + vb.y),
                     to_tf32(va.z + vb.z), to_tf32(va.w + vb.w) };
        *(uint4*)(As + r*AP + c4*4) = ta;
    }
    if (tid < 128) {
        biasS[tid]       = b0[tid];
        biasS[128 + tid] = b1[tid];
        biasS[256 + tid] = b2[tid];
        biasS[384 + tid] = b3[tid];
    }
    __syncthreads();

    #pragma unroll
    for (int w = 0; w < 4; w++) {
        const float* Wp = (w == 0) ? W0 : (w == 1) ? W1 : (w == 2) ? W2 : W3;
        float* Cp       = (w == 0) ? C0 : (w == 1) ? C1 : (w == 2) ? C2 : C3;

        float acc[4][4][4] = {};

        #pragma unroll
        for (int c = 0; c < 4; c++) {          // K chunks of 32
            const int kc = c * 32;
            float4 lw[4];
            #pragma unroll
            for (int q = 0; q < 4; q++) {
                int j = tid + q*256;           // 0..1023
                int r = j >> 3, c8 = j & 7;
                lw[q] = *(const float4*)(Wp + (size_t)r*128 + kc + c8*4);
            }
            __syncthreads();                   // prior compute done before overwrite
            #pragma unroll
            for (int q = 0; q < 4; q++) {
                int j = tid + q*256;
                int r = j >> 3, c8 = j & 7;
                uint4 uw = { to_tf32(lw[q].x), to_tf32(lw[q].y), to_tf32(lw[q].z), to_tf32(lw[q].w) };
                *(uint4*)(Ws + r*WP2 + c8*4) = uw;
            }
            __syncthreads();

            #pragma unroll
            for (int k0 = 0; k0 < 32; k0 += 8) {
                uint32_t af[4][4], bf[4][2];
                #pragma unroll
                for (int mt = 0; mt < 4; mt++) {
                    const uint32_t* ap = As + (wm + mt*16 + g)*AP + kc + k0;
                    af[mt][0] = ap[tg];
                    af[mt][1] = ap[8*AP + tg];
                    af[mt][2] = ap[tg + 4];
                    af[mt][3] = ap[8*AP + tg + 4];
                }
                #pragma unroll
                for (int nt = 0; nt < 4; nt++) {
                    const uint32_t* bp = Ws + (wn + nt*8 + g)*WP2 + k0;
                    bf[nt][0] = bp[tg];
                    bf[nt][1] = bp[tg + 4];
                }
                #pragma unroll
                for (int mt = 0; mt < 4; mt++)
                    #pragma unroll
                    for (int nt = 0; nt < 4; nt++)
                        mma_tf32(acc[mt][nt], af[mt], bf[nt]);
            }
        }

        // epilogue for matrix w
        #pragma unroll
        for (int mt = 0; mt < 4; mt++) {
            #pragma unroll
            for (int nt = 0; nt < 4; nt++) {
                int col = wn + nt*8 + tg*2;
                float bb0 = biasS[w*128 + col], bb1 = biasS[w*128 + col + 1];
                #pragma unroll
                for (int half = 0; half < 2; half++) {
                    size_t row = row0 + wm + mt*16 + g + half*8;
                    float v0 = acc[mt][nt][half*2+0] + bb0;
                    float v1 = acc[mt][nt][half*2+1] + bb1;
                    if (w == 2) { v0 = logsig(v0); v1 = logsig(v1); }
                    *(float2*)(Cp + row*128 + col) = make_float2(v0, v1);
                }
            }
        }
    }
}

// ---------------- final Wc GEMM (chunked W, 2 CTA/SM, residual epilogue) -----
// out[M,128] = att[M,128] @ Wc^T + bc + input - 2*ipos
#define WC_SMEM ((128*AP + 128*WP2 + 256) * 4)   // 87040 bytes

__global__ __launch_bounds__(256, 2)
void gemm_wc(const float* __restrict__ A, const float* __restrict__ W,
             const float* __restrict__ bias, float* __restrict__ C,
             const float* __restrict__ res1, const float* __restrict__ res2) {
    extern __shared__ uint32_t sm[];
    uint32_t* As = sm;                       // 128 x AP
    uint32_t* Ws = sm + 128*AP;              // 128 x WP2
    float* biasS = (float*)(sm + 128*AP + 128*WP2);   // 128

    const int tid  = threadIdx.x;
    const int lane = tid & 31;
    const int wid  = tid >> 5;
    const int g  = lane >> 2;
    const int tg = lane & 3;
    const int wm = (wid & 1) * 64;
    const int wn = (wid >> 1) * 32;
    const size_t row0 = (size_t)blockIdx.x * 128;

    // ---- stage A tile (tf32) + bias ----
    #pragma unroll
    for (int i = tid; i < 4096; i += 256) {
        int r = i >> 5, c4 = i & 31;
        float4 va = ((const float4*)(A + (row0 + r) * 128))[c4];
        uint4 ta = { to_tf32(va.x), to_tf32(va.y), to_tf32(va.z), to_tf32(va.w) };
        *(uint4*)(As + r*AP + c4*4) = ta;
    }
    if (tid < 128) biasS[tid] = bias[tid];
    __syncthreads();

    float acc[4][4][4] = {};

    #pragma unroll
    for (int c = 0; c < 4; c++) {          // K chunks of 32
        const int kc = c * 32;
        float4 lw[4];
        #pragma unroll
        for (int q = 0; q < 4; q++) {
            int j = tid + q*256;
            int r = j >> 3, c8 = j & 7;
            lw[q] = *(const float4*)(W + (size_t)r*128 + kc + c8*4);
        }
        __syncthreads();
        #pragma unroll
        for (int q = 0; q < 4; q++) {
            int j = tid + q*256;
            int r = j >> 3, c8 = j & 7;
            uint4 uw = { to_tf32(lw[q].x), to_tf32(lw[q].y), to_tf32(lw[q].z), to_tf32(lw[q].w) };
            *(uint4*)(Ws + r*WP2 + c8*4) = uw;
        }
        __syncthreads();

        #pragma unroll
        for (int k0 = 0; k0 < 32; k0 += 8) {
            uint32_t af[4][4], bf[4][2];
            #pragma unroll
            for (int mt = 0; mt < 4; mt++) {
                const uint32_t* ap = As + (wm + mt*16 + g)*AP + kc + k0;
                af[mt][0] = ap[tg];
                af[mt][1] = ap[8*AP + tg];
                af[mt][2] = ap[tg + 4];
                af[mt][3] = ap[8*AP + tg + 4];
            }
            #pragma unroll
            for (int nt = 0; nt < 4; nt++) {
                const uint32_t* bp = Ws + (wn + nt*8 + g)*WP2 + k0;
                bf[nt][0] = bp[tg];
                bf[nt][1] = bp[tg + 4];
            }
            #pragma unroll
            for (int mt = 0; mt < 4; mt++)
                #pragma unroll
                for (int nt = 0; nt < 4; nt++)
                    mma_tf32(acc[mt][nt], af[mt], bf[nt]);
        }
    }

    // ---- epilogue: + bias + res1 - 2*res2 ----
    #pragma unroll
    for (int mt = 0; mt < 4; mt++) {
        #pragma unroll
        for (int nt = 0; nt < 4; nt++) {
            int col = wn + nt*8 + tg*2;
            float b0 = biasS[col], b1 = biasS[col+1];
            #pragma unroll
            for (int half = 0; half < 2; half++) {
                size_t row = row0 + wm + mt*16 + g + half*8;
                size_t idx = row*128 + col;
                float2 r1 = *(const float2*)(res1 + idx);
                float2 r2 = *(const float2*)(res2 + idx);
                float v0 = acc[mt][nt][half*2+0] + b0 + r1.x - r2.x;
                float v1 = acc[mt][nt][half*2+1] + b1 + r1.y - r2.y;
                *(float2*)(C + idx) = make_float2(v0, v1);
            }
        }
    }
}

// ---------------- tensor-core attention (R12-proven, P smem buffer) ----------
// One CTA per (t,b,h): 128 threads, 4 warps, warp handles 32 query rows.
#define QS_OFF   0
#define KS_OFF   2560
#define LS_OFF   5120
#define PB_OFF   8192
#define EM_OFF   (8192 + 4*1152)      // 12800
#define ATTN_SMEM ((12800 + 128) * 4) // 51712 bytes

__global__ __launch_bounds__(128)
void attn_tc(const float* __restrict__ gq, const float* __restrict__ gk,
             const float* __restrict__ gl, const float* __restrict__ gr,
             float* __restrict__ ga) {
    extern __shared__ float smf[];
    uint32_t* qs = (uint32_t*)(smf + QS_OFF);   // pitch 20, tf32, pre-scaled 0.25
    uint32_t* ks = (uint32_t*)(smf + KS_OFF);   // pitch 20, tf32
    uint32_t* ls = (uint32_t*)(smf + LS_OFF);   // pitch 24, tf32
    float*    em = smf + EM_OFF;

    const int tid  = threadIdx.x;
    const int lane = tid & 31;
    const int wid  = tid >> 5;
    const int g  = lane >> 2;
    const int tg = lane & 3;
    const int blk = blockIdx.x;
    const int h = blk & 7;
    const int b = (blk >> 3) & 31;
    const int t = blk >> 8;
    const int tok0 = (t*B_ + b)*N_;
    uint32_t* pb = (uint32_t*)(smf + PB_OFF) + wid*1152;   // 32 x 36 per warp

    #pragma unroll
    for (int i = tid; i < 512; i += 128) {
        int token = i >> 2, d4 = i & 3;
        const float* src = gq + ((size_t)(tok0 + token))*F_ + h*16 + d4*4;
        float4 v = *(const float4*)src;
        uint4 u = { to_tf32(v.x*0.25f), to_tf32(v.y*0.25f), to_tf32(v.z*0.25f), to_tf32(v.w*0.25f) };
        *(uint4*)(qs + token*20 + d4*4) = u;
        src = gk + ((size_t)(tok0 + token))*F_ + h*16 + d4*4;
        v = *(const float4*)src;
        uint4 uk = { to_tf32(v.x), to_tf32(v.y), to_tf32(v.z), to_tf32(v.w) };
        *(uint4*)(ks + token*20 + d4*4) = uk;
        src = gl + ((size_t)(tok0 + token))*F_ + h*16 + d4*4;
        v = *(const float4*)src;
        uint4 ul = { to_tf32(v.x), to_tf32(v.y), to_tf32(v.z), to_tf32(v.w) };
        *(uint4*)(ls + token*24 + d4*4) = ul;
    }
    em[tid] = g_mk[b*N_ + tid];
    __syncthreads();

    const int row0w = wid * 32;
    uint32_t af[2][2][4];
    #pragma unroll
    for (int mt = 0; mt < 2; mt++)
        #pragma unroll
        for (int ks2 = 0; ks2 < 2; ks2++) {
            int r0 = row0w + mt*16;
            af[mt][ks2][0] = qs[(r0 + g)*20 + ks2*8 + tg];
            af[mt][ks2][1] = qs[(r0 + g + 8)*20 + ks2*8 + tg];
            af[mt][ks2][2] = qs[(r0 + g)*20 + ks2*8 + tg + 4];
            af[mt][ks2][3] = qs[(r0 + g + 8)*20 + ks2*8 + tg + 4];
        }

    float oac[2][2][4] = {};
    float ps[2][2] = {};

    #pragma unroll
    for (int c = 0; c < 4; c++) {
        const int keys0 = c * 32;
        #pragma unroll
        for (int nt = 0; nt < 4; nt++) {
            const int n0 = keys0 + nt*8;
            uint32_t bf[2][2];
            #pragma unroll
            for (int ks2 = 0; ks2 < 2; ks2++) {
                bf[ks2][0] = ks[(n0 + g)*20 + ks2*8 + tg];
                bf[ks2][1] = ks[(n0 + g)*20 + ks2*8 + tg + 4];
            }
            float2 emv = *(const float2*)(em + n0 + 2*tg);
            #pragma unroll
            for (int mt = 0; mt < 2; mt++) {
                float d[4] = {0.f, 0.f, 0.f, 0.f};
                mma_tf32(d, af[mt][0], bf[0]);
                mma_tf32(d, af[mt][1], bf[1]);
                float e0 = fexp_nc(d[0]) * emv.x;
                float e1 = fexp_nc(d[1]) * emv.y;
                float e2 = fexp_nc(d[2]) * emv.x;
                float e3 = fexp_nc(d[3]) * emv.y;
                ps[mt][0] += e0 + e1;
                ps[mt][1] += e2 + e3;
                uint32_t* p0 = pb + (mt*16 + g)*36 + nt*8 + 2*tg;
                p0[0] = to_tf32(e0); p0[1] = to_tf32(e1);
                uint32_t* p1 = pb + (mt*16 + g + 8)*36 + nt*8 + 2*tg;
                p1[0] = to_tf32(e2); p1[1] = to_tf32(e3);
            }
        }
        __syncwarp();
        #pragma unroll
        for (int kk = 0; kk < 4; kk++) {
            uint32_t bl[2][2];
            #pragma unroll
            for (int nt2 = 0; nt2 < 2; nt2++) {
                bl[nt2][0] = ls[(keys0 + kk*8 + tg)*24 + nt2*8 + g];
                bl[nt2][1] = ls[(keys0 + kk*8 + tg + 4)*24 + nt2*8 + g];
            }
            #pragma unroll
            for (int mt = 0; mt < 2; mt++) {
                uint32_t ap[4];
                ap[0] = pb[(mt*16 + g)*36 + kk*8 + tg];
                ap[1] = pb[(mt*16 + g + 8)*36 + kk*8 + tg];
                ap[2] = pb[(mt*16 + g)*36 + kk*8 + tg + 4];
                ap[3] = pb[(mt*16 + g + 8)*36 + kk*8 + tg + 4];
                #pragma unroll
                for (int nt2 = 0; nt2 < 2; nt2++)
                    mma_tf32(oac[mt][nt2], ap, bl[nt2]);
            }
        }
        __syncwarp();
    }

    float inv[2][2];
    #pragma unroll
    for (int mt = 0; mt < 2; mt++)
        #pragma unroll
        for (int hf = 0; hf < 2; hf++) {
            float s = ps[mt][hf];
            s += __shfl_xor_sync(0xFFFFFFFF, s, 1);
            s += __shfl_xor_sync(0xFFFFFFFF, s, 2);
            inv[mt][hf] = 1.0f / s;
        }

    #pragma unroll
    for (int mt = 0; mt < 2; mt++)
        #pragma unroll
        for (int hf = 0; hf < 2; hf++) {
            int row = row0w + mt*16 + g + hf*8;
            size_t base = ((size_t)(tok0 + row))*F_ + h*16;
            #pragma unroll
            for (int nt2 = 0; nt2 < 2; nt2++) {
                int col = nt2*8 + 2*tg;
                float2 rv = *(const float2*)(gr + base + col);
                float o0 = rv.x * fexp(oac[mt][nt2][hf*2+0] * inv[mt][hf]);
                float o1 = rv.y * fexp(oac[mt][nt2][hf*2+1] * inv[mt][hf]);
                *(float2*)(ga + base + col) = make_float2(o0, o1);
            }
        }
}

// ---------------- launch -----------------------------------------------------
extern "C" void kernel_launch(void* const* d_in, const int* in_sizes, int n_in,
                              void* d_out, int out_size) {
    const float* input = (const float*)d_in[0];
    const float* ipos  = (const float*)d_in[1];
    const int*   mask  = (const int*)d_in[2];
    const float* Wq = (const float*)d_in[3];  const float* bq = (const float*)d_in[4];
    const float* Wk = (const float*)d_in[5];  const float* bk = (const float*)d_in[6];
    const float* Wv = (const float*)d_in[7];  const float* bv = (const float*)d_in[8];
    const float* Wr = (const float*)d_in[9];  const float* br = (const float*)d_in[10];
    const float* Wc = (const float*)d_in[11]; const float* bc = (const float*)d_in[12];
    float* out = (float*)d_out;

    float *pq, *pk, *pl, *pr, *pa;
    cudaGetSymbolAddress((void**)&pq, g_q);
    cudaGetSymbolAddress((void**)&pk, g_k);
    cudaGetSymbolAddress((void**)&pl, g_lsv);
    cudaGetSymbolAddress((void**)&pr, g_r);
    cudaGetSymbolAddress((void**)&pa, g_att);

    cudaFuncSetAttribute(gemm_qkvr, cudaFuncAttributeMaxDynamicSharedMemorySize, QKVR_SMEM);
    cudaFuncSetAttribute(gemm_wc,   cudaFuncAttributeMaxDynamicSharedMemorySize, WC_SMEM);
    cudaFuncSetAttribute(attn_tc,   cudaFuncAttributeMaxDynamicSharedMemorySize, ATTN_SMEM);

    mask_kernel<<<(B_*N_ + 127)/128, 128>>>(mask);

    const int MBLK = TOK / 128;   // 960
    gemm_qkvr<<<MBLK, 256, QKVR_SMEM>>>(input, ipos, Wq, Wk, Wv, Wr,
                                        bq, bk, bv, br,
                                        pq, pk, pl, pr);

    attn_tc<<<T_*B_*H_, 128, ATTN_SMEM>>>(pq, pk, pl, pr, pa);

    gemm_wc<<<MBLK, 256, WC_SMEM>>>(pa, Wc, bc, out, input, ipos);
}